// round 8
// baseline (speedup 1.0000x reference)
#include <cuda_runtime.h>
#include <cuda_fp16.h>
#include <cstdint>

#define TOKENS   64
#define NFEAT    8192
#define KFEAT    8192

#define KSPLIT    4
#define K_PER_CTA (KFEAT / KSPLIT)      // 2048 codes
#define CTA_N     128                   // 8 warps x 16 channels
#define ITER_C    64                    // codes per iteration
#define NITER     (K_PER_CTA / ITER_C)  // 32
#define PITCH     72                    // halves per smem A row (144B, conflict-free)
#define ASTAGES   4

// scratch
__device__ __align__(16) __half g_x16[TOKENS * KFEAT];            // 1MB, K-permuted fp16 x
__device__ float g_sumx4[TOKENS * 4];
__device__ __align__(16) float g_part[KSPLIT][TOKENS * NFEAT];    // 8MB
__device__ unsigned g_bar;                                        // global barrier (monotonic)
__device__ unsigned g_tilecnt[NFEAT / CTA_N];                     // per-tile finalize counters

// ---------------------------------------------------------------------------
__device__ __forceinline__ void cpa16(uint32_t dst, const void* src) {
    asm volatile("cp.async.ca.shared.global [%0], [%1], 16;\n" :: "r"(dst), "l"(src));
}
#define CP_COMMIT() asm volatile("cp.async.commit_group;\n" ::: "memory")
#define CP_WAIT2()  asm volatile("cp.async.wait_group 2;\n" ::: "memory")

// [a.b0, 0, b.b0, 0] -> half2 {ca*2^-24, cb*2^-24} (exact), one PRMT.
__device__ __forceinline__ uint32_t pack2(uint32_t a, uint32_t b) {
    uint32_t r;
    asm("prmt.b32 %0, %1, %2, 0x5410;" : "=r"(r) : "r"(a), "r"(b));
    return r;
}
__device__ __forceinline__ void mma16816(float* d, const uint32_t* a, uint32_t b0, uint32_t b1) {
    asm volatile(
        "mma.sync.aligned.m16n8k16.row.col.f32.f16.f16.f32 "
        "{%0,%1,%2,%3},{%4,%5,%6,%7},{%8,%9},{%0,%1,%2,%3};"
        : "+f"(d[0]), "+f"(d[1]), "+f"(d[2]), "+f"(d[3])
        : "r"(a[0]), "r"(a[1]), "r"(a[2]), "r"(a[3]), "r"(b0), "r"(b1));
}

// ---------------------------------------------------------------------------
// Fused kernel: prep (1/256 slice each) -> global barrier -> GEMM -> finalize.
// grid (64 tiles, 4 ksplits) x 256 threads; one resident wave (<=296 slots).
// ---------------------------------------------------------------------------
__global__ __launch_bounds__(256, 2) void fused_kernel(
    const float* __restrict__ x, const int* __restrict__ q,
    const float* __restrict__ scales, const int* __restrict__ zp,
    const float* __restrict__ bias, float* __restrict__ out) {

    __shared__ __align__(16) __half sA[ASTAGES][TOKENS * PITCH];   // 4 x 9216 B
    __shared__ float s_red[256];
    __shared__ unsigned s_old;

    const int tid  = threadIdx.x;
    const int warp = tid >> 5;
    const int lane = tid & 31;
    const int bx = blockIdx.x;          // 0..63  (N tile / prep token)
    const int by = blockIdx.y;          // 0..3   (K split / prep quarter)

    // ===================== phase 1: prep my x slice =====================
    // CTA (bx,by) handles token bx, quarter by: 2048 codes. Thread: half a
    // 16-code group (8 dest codes); dest word w sources floats {h*2+4w, +1}.
    {
        const int gl = tid >> 1, h = tid & 1;
        const int g = by * 128 + gl;                   // group within token row
        const float2* src = reinterpret_cast<const float2*>(
            x + (size_t)bx * KFEAT + g * 16 + h * 2);
        float2 f0 = src[0], f1 = src[2], f2 = src[4], f3 = src[6];
        __half2 q0 = __floats2half2_rn(f0.x, f0.y);
        __half2 q1 = __floats2half2_rn(f1.x, f1.y);
        __half2 q2 = __floats2half2_rn(f2.x, f2.y);
        __half2 q3 = __floats2half2_rn(f3.x, f3.y);
        float sm = (__low2float(q0) + __high2float(q0)) + (__low2float(q1) + __high2float(q1))
                 + (__low2float(q2) + __high2float(q2)) + (__low2float(q3) + __high2float(q3));
        reinterpret_cast<uint4*>(g_x16)[bx * 1024 + g * 2 + h] =
            make_uint4(*(uint32_t*)&q0, *(uint32_t*)&q1, *(uint32_t*)&q2, *(uint32_t*)&q3);
        s_red[tid] = sm; __syncthreads();
        for (int s = 128; s > 0; s >>= 1) {
            if (tid < s) s_red[tid] += s_red[tid + s];
            __syncthreads();
        }
        if (tid == 0) g_sumx4[bx * 4 + by] = s_red[0];
    }

    // ===================== GEMM setup + B prologue (pre-barrier) ========
    const int n0 = bx * CTA_N + warp * 16;
    const int kb = by * K_PER_CTA;

    const int r0 = n0 + (lane >> 2);
    const int r1 = r0 + 8;
    const int qd4 = (lane & 3) * 4;
    const int* pB0 = q + (size_t)r0 * KFEAT + kb + qd4;
    const int* pB1 = q + (size_t)r1 * KFEAT + kb + qd4;

    int4 raw[2][4];
#pragma unroll
    for (int s = 0; s < 4; s++) {
        raw[0][s] = __ldcs((const int4*)(pB0 + s * 16));
        raw[1][s] = __ldcs((const int4*)(pB1 + s * 16));
    }

    // ===================== global barrier (resident wave) ===============
    __threadfence();
    __syncthreads();
    if (tid == 0) {
        unsigned old = atomicAdd(&g_bar, 1u);
        unsigned target = ((old >> 8) + 1u) << 8;
        while (*((volatile unsigned*)&g_bar) < target) { }
        s_old = 0;  // reuse later; also serves as dummy
    }
    __syncthreads();
    __threadfence();

    // ===================== phase 2: GEMM ================================
    const int arow = tid >> 2;
    const int aseg = tid & 3;
    const __half* asrc = g_x16 + (size_t)arow * KFEAT + kb + aseg * 8;
    const uint32_t sbase = (uint32_t)__cvta_generic_to_shared(&sA[0][0]);
    const uint32_t ABUF  = TOKENS * PITCH * 2;
    const uint32_t adst  = (uint32_t)(arow * PITCH + aseg * 8) * 2;

#pragma unroll
    for (int i = 0; i < 3; i++) {
        cpa16(sbase + i * ABUF + adst, asrc + (size_t)i * ITER_C);
        cpa16(sbase + i * ABUF + adst + 64, asrc + (size_t)i * ITER_C + 32);
        CP_COMMIT();
    }

    float acc[4][2][4];
#pragma unroll
    for (int mi = 0; mi < 4; mi++)
#pragma unroll
        for (int nf = 0; nf < 2; nf++)
#pragma unroll
            for (int j = 0; j < 4; j++) acc[mi][nf][j] = 0.f;

    const int rl = lane & 15;
    const int kh = (lane >> 4) * 8;

    for (int i = 0; i < NITER; i++) {
        CP_WAIT2();
        __syncthreads();

        if (i + 3 < NITER) {
            const __half* s3 = asrc + (size_t)(i + 3) * ITER_C;
            cpa16(sbase + ((i + 3) & 3) * ABUF + adst, s3);
            cpa16(sbase + ((i + 3) & 3) * ABUF + adst + 64, s3 + 32);
        }
        CP_COMMIT();

        uint32_t bf[2][4][2];
#pragma unroll
        for (int nf = 0; nf < 2; nf++)
#pragma unroll
            for (int s = 0; s < 4; s++) {
                int4 w = raw[nf][s];
                bf[nf][s][0] = pack2((uint32_t)w.x, (uint32_t)w.y);
                bf[nf][s][1] = pack2((uint32_t)w.z, (uint32_t)w.w);
            }

        if (i + 1 < NITER) {
            const int off = (i + 1) * ITER_C;
#pragma unroll
            for (int s = 0; s < 4; s++) {
                raw[0][s] = __ldcs((const int4*)(pB0 + off + s * 16));
                raw[1][s] = __ldcs((const int4*)(pB1 + off + s * 16));
            }
        }

        const uint32_t abase = sbase + (uint32_t)(i & 3) * ABUF;
#pragma unroll
        for (int s = 0; s < 4; s++) {
            uint32_t a[4][4];
#pragma unroll
            for (int mi = 0; mi < 4; mi++) {
                uint32_t addr = abase + (uint32_t)((mi * 16 + rl) * PITCH + s * 16 + kh) * 2;
                asm volatile(
                    "ldmatrix.sync.aligned.m8n8.x4.shared.b16 {%0,%1,%2,%3}, [%4];"
                    : "=r"(a[mi][0]), "=r"(a[mi][1]), "=r"(a[mi][2]), "=r"(a[mi][3])
                    : "r"(addr));
            }
#pragma unroll
            for (int mi = 0; mi < 4; mi++)
#pragma unroll
                for (int nf = 0; nf < 2; nf++)
                    mma16816(acc[mi][nf], a[mi], bf[nf][s][0], bf[nf][s][1]);
        }
    }

    // epilogue: raw partial dots
    {
        float* pp = &g_part[by][0];
        const int kc2 = (lane & 3) * 2;
#pragma unroll
        for (int mi = 0; mi < 4; mi++)
#pragma unroll
            for (int nf = 0; nf < 2; nf++) {
                int col = n0 + nf * 8 + kc2;
                int t0  = mi * 16 + (lane >> 2);
                *reinterpret_cast<float2*>(&pp[(size_t)t0 * NFEAT + col]) =
                    make_float2(acc[mi][nf][0], acc[mi][nf][1]);
                *reinterpret_cast<float2*>(&pp[(size_t)(t0 + 8) * NFEAT + col]) =
                    make_float2(acc[mi][nf][2], acc[mi][nf][3]);
            }
    }

    // ===================== phase 3: per-tile finalize ===================
    __threadfence();
    __syncthreads();
    if (tid == 0) s_old = atomicAdd(&g_tilecnt[bx], 1u);
    __syncthreads();
    if ((s_old & 3u) == 3u) {
        __threadfence();
        const float SC = 16777216.0f;  // 2^24
        // tile bx: 64 tok x 128 ch = 2048 float4 units; 8 per thread
        for (int i = tid; i < TOKENS * (CTA_N / 4); i += 256) {
            int t  = i >> 5;                      // token
            int c4 = i & 31;                      // float4 within tile
            size_t idx = (size_t)t * (NFEAT / 4) + bx * (CTA_N / 4) + c4;
            float4 a = reinterpret_cast<const float4*>(g_part[0])[idx];
            float4 b = reinterpret_cast<const float4*>(g_part[1])[idx];
            float4 c = reinterpret_cast<const float4*>(g_part[2])[idx];
            float4 d = reinterpret_cast<const float4*>(g_part[3])[idx];
            int gcol4 = bx * (CTA_N / 4) + c4;
            float4 sc = reinterpret_cast<const float4*>(scales)[gcol4];
            float4 bi = reinterpret_cast<const float4*>(bias)[gcol4];
            int4   zi = reinterpret_cast<const int4*>(zp)[gcol4];
            float sx = (g_sumx4[t * 4 + 0] + g_sumx4[t * 4 + 1]) +
                       (g_sumx4[t * 4 + 2] + g_sumx4[t * 4 + 3]);
            float4 r;
            r.x = bi.x + sc.x * (SC * ((a.x + b.x) + (c.x + d.x)) - (float)zi.x * sx);
            r.y = bi.y + sc.y * (SC * ((a.y + b.y) + (c.y + d.y)) - (float)zi.y * sx);
            r.z = bi.z + sc.z * (SC * ((a.z + b.z) + (c.z + d.z)) - (float)zi.z * sx);
            r.w = bi.w + sc.w * (SC * ((a.w + b.w) + (c.w + d.w)) - (float)zi.w * sx);
            reinterpret_cast<float4*>(out)[idx] = r;
        }
    }
}

// ---------------------------------------------------------------------------
extern "C" void kernel_launch(void* const* d_in, const int* in_sizes, int n_in,
                              void* d_out, int out_size) {
    const float* x    = (const float*)d_in[0];
    const int*   qw   = (const int*)d_in[1];
    const float* sc   = (const float*)d_in[2];
    const int*   zp   = (const int*)d_in[3];
    const float* bias = (const float*)d_in[4];
    float*       out  = (float*)d_out;
    (void)in_sizes; (void)n_in; (void)out_size;

    fused_kernel<<<dim3(NFEAT / CTA_N, KSPLIT), 256>>>(x, qw, sc, zp, bias, out);
}